// round 2
// baseline (speedup 1.0000x reference)
#include <cuda_runtime.h>
#include <math.h>

// Problem constants
#define Bq   64
#define Tq   256
#define Cq   2048
#define WEq  256
#define Hq   1024
#define G3q  3072
#define SPLITS 8   // split-K for the per-step gh GEMM

// ---------------- scratch (device globals; no allocations allowed) ----------
__device__ float d_X  [Tq * Bq * WEq];        //  16.8 MB  embedded inputs
__device__ float d_gi [(size_t)Tq * Bq * G3q];// 201   MB  input-gate preacts
__device__ float d_H  [(Tq + 1) * Bq * Hq];   //  67   MB  h_0..h_T
__device__ float d_ghp[SPLITS * Bq * G3q];    //   6.3 MB  split-K partials
__device__ float d_e  [Tq * Bq * Tq];         //  16.8 MB  attention scores/alpha
__device__ float d_ctx[(size_t)Tq * Bq * Hq]; //  67   MB  contexts
__device__ int   d_words[Bq];

// ---------------- f32x2 helpers ---------------------------------------------
typedef unsigned long long u64;

__device__ __forceinline__ void ffma2(u64& d, u64 a, u64 b) {
    asm("fma.rn.f32x2 %0, %1, %2, %0;" : "+l"(d) : "l"(a), "l"(b));
}
__device__ __forceinline__ float2 u2f2(u64 v) {
    unsigned lo, hi;
    asm("mov.b64 {%0, %1}, %2;" : "=r"(lo), "=r"(hi) : "l"(v));
    return make_float2(__uint_as_float(lo), __uint_as_float(hi));
}

// ---------------- generic f32x2 tile GEMM ------------------------------------
// C[m, n] (+=) sum_k A[m, k] * B[n, k] (+ bias[n])
// A: row m at Ab + m*lda, k contiguous.
// B (BNC=false): row n at Bb + n*ldb, k contiguous.
// B (BNC=true) : element (n, k) at Bb + k*ldb + n   (n contiguous).
// blockIdx.z batches: pointers advance by a_bs/b_bs/c_bs elements.
// swapf: output row index = (m%64)*256 + m/64  (maps m=t*B+b -> b*T+t).
#define BM 64
#define BN 64
#define BK 16

template <bool BNC>
__global__ __launch_bounds__(128) void gemm_k(
    const float* __restrict__ A, const float* __restrict__ Bm,
    float* __restrict__ Cm, int K,
    int lda, int ldb, int ldc,
    long long a_bs, long long b_bs, long long c_bs,
    const float* __restrict__ bias, int accf, int swapf)
{
    __shared__ float As2[BK][2 * BM];  // A duplicated per element -> LDS.64 gives {a,a}
    __shared__ float Bs [BK][BN];

    const int tid = threadIdx.x;          // 128 threads
    const int tx  = tid & 15;             // n / 4
    const int ty  = tid >> 4;             // m / 8
    const int n0  = blockIdx.x * BN;
    const int m0  = blockIdx.y * BM;
    const float* Ab = A  + (size_t)blockIdx.z * a_bs;
    const float* Bb = Bm + (size_t)blockIdx.z * b_bs;
    float*       Cb = Cm + (size_t)blockIdx.z * c_bs;

    u64 acc[8][2];
#pragma unroll
    for (int i = 0; i < 8; i++) { acc[i][0] = 0ull; acc[i][1] = 0ull; }

    const int ar0 = tid >> 2;             // 0..31
    const int ac0 = (tid & 3) * 4;        // 0,4,8,12
    const int ar1 = ar0 + 32;

    const float* Ap0 = Ab + (size_t)(m0 + ar0) * lda + ac0;
    const float* Ap1 = Ab + (size_t)(m0 + ar1) * lda + ac0;
    const float* Bp0;
    const float* Bp1;
    int bk0 = 0, bn0v = 0;
    if (!BNC) {
        Bp0 = Bb + (size_t)(n0 + ar0) * ldb + ac0;
        Bp1 = Bb + (size_t)(n0 + ar1) * ldb + ac0;
    } else {
        bk0  = tid >> 4;                  // 0..7
        bn0v = (tid & 15) * 4;            // 0..60
        Bp0 = Bb + (size_t)bk0 * ldb + n0 + bn0v;
        Bp1 = Bb + (size_t)(bk0 + 8) * ldb + n0 + bn0v;
    }

    for (int k0 = 0; k0 < K; k0 += BK) {
        float4 a0 = *(const float4*)Ap0;  Ap0 += BK;
        float4 a1 = *(const float4*)Ap1;  Ap1 += BK;
        float4 b0, b1;
        if (!BNC) {
            b0 = *(const float4*)Bp0;  Bp0 += BK;
            b1 = *(const float4*)Bp1;  Bp1 += BK;
        } else {
            b0 = *(const float4*)Bp0;  Bp0 += (size_t)BK * ldb;
            b1 = *(const float4*)Bp1;  Bp1 += (size_t)BK * ldb;
        }

        *(float2*)&As2[ac0 + 0][2 * ar0] = make_float2(a0.x, a0.x);
        *(float2*)&As2[ac0 + 1][2 * ar0] = make_float2(a0.y, a0.y);
        *(float2*)&As2[ac0 + 2][2 * ar0] = make_float2(a0.z, a0.z);
        *(float2*)&As2[ac0 + 3][2 * ar0] = make_float2(a0.w, a0.w);
        *(float2*)&As2[ac0 + 0][2 * ar1] = make_float2(a1.x, a1.x);
        *(float2*)&As2[ac0 + 1][2 * ar1] = make_float2(a1.y, a1.y);
        *(float2*)&As2[ac0 + 2][2 * ar1] = make_float2(a1.z, a1.z);
        *(float2*)&As2[ac0 + 3][2 * ar1] = make_float2(a1.w, a1.w);
        if (!BNC) {
            Bs[ac0 + 0][ar0] = b0.x; Bs[ac0 + 1][ar0] = b0.y;
            Bs[ac0 + 2][ar0] = b0.z; Bs[ac0 + 3][ar0] = b0.w;
            Bs[ac0 + 0][ar1] = b1.x; Bs[ac0 + 1][ar1] = b1.y;
            Bs[ac0 + 2][ar1] = b1.z; Bs[ac0 + 3][ar1] = b1.w;
        } else {
            *(float4*)&Bs[bk0][bn0v]     = b0;
            *(float4*)&Bs[bk0 + 8][bn0v] = b1;
        }
        __syncthreads();

#pragma unroll
        for (int k = 0; k < BK; k++) {
            u64 bl = *(const u64*)&Bs[k][tx * 4];
            u64 bh = *(const u64*)&Bs[k][tx * 4 + 2];
#pragma unroll
            for (int mi = 0; mi < 8; mi++) {
                u64 ad = *(const u64*)&As2[k][(ty * 8 + mi) * 2];
                ffma2(acc[mi][0], ad, bl);
                ffma2(acc[mi][1], ad, bh);
            }
        }
        __syncthreads();
    }

    float4 bv = make_float4(0.f, 0.f, 0.f, 0.f);
    if (bias) bv = *(const float4*)(bias + n0 + tx * 4);
#pragma unroll
    for (int mi = 0; mi < 8; mi++) {
        int m = m0 + ty * 8 + mi;
        size_t row = swapf ? ((size_t)(m & 63) * Tq + (m >> 6)) : (size_t)m;
        float* cp = Cb + row * (size_t)ldc + n0 + tx * 4;
        float2 lo = u2f2(acc[mi][0]);
        float2 hi = u2f2(acc[mi][1]);
        float4 v = make_float4(lo.x + bv.x, lo.y + bv.y, hi.x + bv.z, hi.y + bv.w);
        if (accf) {
            float4 o = *(const float4*)cp;
            v.x += o.x; v.y += o.y; v.z += o.z; v.w += o.w;
        }
        *(float4*)cp = v;
    }
}

// ---------------- small kernels ----------------------------------------------
__global__ void embed_k(const int* __restrict__ targets, const float* __restrict__ E)
{
    int m = blockIdx.x;                 // t*B + b
    int t = m >> 6, b = m & 63;
    int id = (t == 0) ? 0 : targets[b * Tq + (t - 1)];
    const float4* src = (const float4*)(E + (size_t)id * WEq);
    float4* dst = (float4*)(d_X + (size_t)m * WEq);
    dst[threadIdx.x] = src[threadIdx.x];          // 64 threads * float4 = 256
}

// mask is a prefix mask (arange(T) < words_num). Count true entries per row.
// Element width auto-detected: byte 1 of the buffer is nonzero iff elements are
// 1 byte wide (mask[0][1] is guaranteed true since words_num >= T/2).
__global__ void words_k(const unsigned char* __restrict__ mask8)
{
    int b = blockIdx.x, t = threadIdx.x;          // 256 threads
    int is8 = (mask8[1] != 0);
    int v;
    if (is8) v = mask8[b * Tq + t] ? 1 : 0;
    else     v = ((const int*)mask8)[b * Tq + t] ? 1 : 0;
#pragma unroll
    for (int o = 16; o; o >>= 1) v += __shfl_down_sync(0xffffffffu, v, o);
    __shared__ int red[8];
    if ((t & 31) == 0) red[t >> 5] = v;
    __syncthreads();
    if (t == 0) {
        int s = 0;
#pragma unroll
        for (int i = 0; i < 8; i++) s += red[i];
        d_words[b] = s;
    }
}

__global__ void h0_k(const float* __restrict__ enc)
{
    int b = blockIdx.x;
    const float4* src = (const float4*)(enc + ((size_t)b * Tq + (Tq - 1)) * Hq);
    float4* dst = (float4*)(d_H + (size_t)b * Hq);
    dst[threadIdx.x] = src[threadIdx.x];          // 256 threads * float4 = 1024
}

__global__ void gates_k(const float* __restrict__ b_hh, int t)
{
    int idx = blockIdx.x * 256 + threadIdx.x;     // 0 .. B*H-1
    int b = idx >> 10;
    int j = idx & (Hq - 1);
    float ghr = b_hh[j], ghz = b_hh[Hq + j], ghn = b_hh[2 * Hq + j];
#pragma unroll
    for (int s = 0; s < SPLITS; s++) {
        const float* p = d_ghp + (size_t)s * Bq * G3q + (size_t)b * G3q;
        ghr += p[j]; ghz += p[Hq + j]; ghn += p[2 * Hq + j];
    }
    const float* gi = d_gi + ((size_t)t * Bq + b) * G3q;
    float r = 1.f / (1.f + expf(-(gi[j]          + ghr)));
    float z = 1.f / (1.f + expf(-(gi[Hq + j]     + ghz)));
    float n = tanhf(gi[2 * Hq + j] + r * ghn);
    float hp = d_H[(size_t)t * Bq * Hq + (size_t)b * Hq + j];
    d_H[(size_t)(t + 1) * Bq * Hq + (size_t)b * Hq + j] = (1.f - z) * n + z * hp;
}

__global__ void softmax_k()
{
    int m = blockIdx.x;                 // t*B + b
    int b = m & (Bq - 1);
    int wn = d_words[b];
    float* e = d_e + (size_t)m * Tq;
    int s = threadIdx.x;                // 256
    float v = (s < wn) ? e[s] : -3.0e38f;

    __shared__ float red[8];
    __shared__ float smax, ssum;
    float mx = v;
#pragma unroll
    for (int o = 16; o; o >>= 1) mx = fmaxf(mx, __shfl_xor_sync(0xffffffffu, mx, o));
    if ((s & 31) == 0) red[s >> 5] = mx;
    __syncthreads();
    if (s == 0) {
        float x = red[0];
#pragma unroll
        for (int i = 1; i < 8; i++) x = fmaxf(x, red[i]);
        smax = x;
    }
    __syncthreads();
    float ex = (s < wn) ? expf(v - smax) : 0.f;
    float sum = ex;
#pragma unroll
    for (int o = 16; o; o >>= 1) sum += __shfl_xor_sync(0xffffffffu, sum, o);
    if ((s & 31) == 0) red[s >> 5] = sum;
    __syncthreads();
    if (s == 0) {
        float x = 0.f;
#pragma unroll
        for (int i = 0; i < 8; i++) x += red[i];
        ssum = 1.f / x;
    }
    __syncthreads();
    e[s] = ex * ssum;
}

// ---------------- launch ------------------------------------------------------
extern "C" void kernel_launch(void* const* d_in, const int* in_sizes, int n_in,
                              void* d_out, int out_size)
{
    const float*         enc     = (const float*)d_in[0];
    const unsigned char* mask    = (const unsigned char*)d_in[1];
    const int*           targets = (const int*)d_in[2];
    const float*         E       = (const float*)d_in[3];
    const float*         W_ih    = (const float*)d_in[4];
    const float*         W_hh    = (const float*)d_in[5];
    const float*         b_ih    = (const float*)d_in[6];
    const float*         b_hh    = (const float*)d_in[7];
    const float*         W_out   = (const float*)d_in[8];
    const float*         b_out   = (const float*)d_in[9];
    float* out = (float*)d_out;

    void* p;
    cudaGetSymbolAddress(&p, d_X);   float* X   = (float*)p;
    cudaGetSymbolAddress(&p, d_gi);  float* GI  = (float*)p;
    cudaGetSymbolAddress(&p, d_H);   float* Hh  = (float*)p;
    cudaGetSymbolAddress(&p, d_ghp); float* GHP = (float*)p;
    cudaGetSymbolAddress(&p, d_e);   float* Ee  = (float*)p;
    cudaGetSymbolAddress(&p, d_ctx); float* CTX = (float*)p;

    // Phase 0: embeddings, mask lengths, h0
    embed_k<<<Tq * Bq, 64>>>(targets, E);
    words_k<<<Bq, 256>>>(mask);
    h0_k<<<Bq, 256>>>(enc);

    // Phase 1: gi = X @ W_ih^T + b_ih        (16384 x 3072 x 256)
    gemm_k<false><<<dim3(G3q / BN, (Tq * Bq) / BM, 1), 128>>>(
        X, W_ih, GI, WEq, WEq, WEq, G3q, 0, 0, 0, b_ih, 0, 0);

    // Phase 2: sequential GRU (only the recurrence; attention/logits deferred)
    for (int t = 0; t < Tq; t++) {
        // gh partials: split-K over K=1024 into 8 chunks of 128
        gemm_k<false><<<dim3(G3q / BN, 1, SPLITS), 128>>>(
            Hh + (size_t)t * Bq * Hq, W_hh, GHP, Hq / SPLITS,
            Hq, Hq, G3q,
            Hq / SPLITS, Hq / SPLITS, (long long)Bq * G3q,
            nullptr, 0, 0);
        gates_k<<<(Bq * Hq) / 256, 256>>>(b_hh, t);
    }

    // Phase 3a: e[t,b,s] = h1[t,b,:] . enc[b,s,:]   (batched over b)
    gemm_k<false><<<dim3(Tq / BN, Tq / BM, Bq), 128>>>(
        Hh + (size_t)Bq * Hq, enc, Ee, Hq,
        Bq * Hq, Hq, Bq * Tq,
        Hq, (long long)Tq * Hq, Tq,
        nullptr, 0, 0);

    // Phase 3b: masked softmax over s
    softmax_k<<<Tq * Bq, Tq>>>();

    // Phase 3c: ctx[t,b,:] = alpha[t,b,:] @ enc[b]  (B is n-contiguous)
    gemm_k<true><<<dim3(Hq / BN, Tq / BM, Bq), 128>>>(
        Ee, enc, CTX, Tq,
        Bq * Tq, Hq, Bq * Hq,
        Tq, (long long)Tq * Hq, Hq,
        nullptr, 0, 0);

    // Phase 4: logits = h1 @ W_out[:, :H]^T + b_out  then += ctx @ W_out[:, H:]^T
    // written directly in (B, T, C) order via swapf
    gemm_k<false><<<dim3(Cq / BN, (Tq * Bq) / BM, 1), 128>>>(
        Hh + (size_t)Bq * Hq, W_out, out, Hq,
        Hq, 2 * Hq, Cq, 0, 0, 0, b_out, 0, 1);
    gemm_k<false><<<dim3(Cq / BN, (Tq * Bq) / BM, 1), 128>>>(
        CTX, W_out + Hq, out, Hq,
        Hq, 2 * Hq, Cq, 0, 0, 0, nullptr, 1, 1);
}

// round 3
// speedup vs baseline: 1.1290x; 1.1290x over previous
#include <cuda_runtime.h>
#include <math.h>

// Problem constants
#define Bq   64
#define Tq   256
#define Cq   2048
#define WEq  256
#define Hq   1024
#define G3q  3072
#define SPLITS 8
#define BK   16

typedef unsigned long long u64;

// ---------------- scratch (device globals) -----------------------------------
__device__ float d_X  [Tq * Bq * WEq];
__device__ float d_gi [(size_t)Tq * Bq * G3q];
__device__ float d_H  [(Tq + 1) * Bq * Hq];
__device__ float d_ghp[SPLITS * Bq * G3q];
__device__ float d_e  [Tq * Bq * Tq];
__device__ float d_ctx[(size_t)Tq * Bq * Hq];
__device__ int   d_words[Bq];

// ---------------- f32x2 helpers ----------------------------------------------
__device__ __forceinline__ void ffma2(u64& d, u64 a, u64 b) {
    asm("fma.rn.f32x2 %0, %1, %2, %0;" : "+l"(d) : "l"(a), "l"(b));
}
__device__ __forceinline__ float2 u2f2(u64 v) {
    unsigned lo, hi;
    asm("mov.b64 {%0, %1}, %2;" : "=r"(lo), "=r"(hi) : "l"(v));
    return make_float2(__uint_as_float(lo), __uint_as_float(hi));
}

// ---------------- f32x2 GEMM, pairs along M ----------------------------------
// C[m, n] (+=) sum_k A[m, k] * B[n, k] (+ bias[n])
// A: row m at k-contiguous (lda). B !BNC: row n k-contiguous (ldb).
// B BNC: element (n,k) at k*ldb + n (n contiguous).
// Per-thread tile: TM rows (as TM/2 f32x2 pairs) x TN cols at n = n0 + j*NTX + tx.
// A stored naturally in smem (m contiguous -> LDS.64 = m-pair); B duplicated {b,b}.
template <int BM, int BN, int TM, int TN, bool BNC>
__global__ __launch_bounds__((BM / TM) * (BN / TN), 2) void gemm2_k(
    const float* __restrict__ A, const float* __restrict__ Bm,
    float* __restrict__ Cm, int K,
    int lda, int ldb, int ldc,
    long long a_bs, long long b_bs, long long c_bs,
    const float* __restrict__ bias, int accf, int swapf)
{
    constexpr int THREADS = (BM / TM) * (BN / TN);
    constexpr int NTX = BN / TN;          // threads along n
    constexpr int NP  = TM / 2;           // m-pairs per thread
    constexpr int NA4 = (BM * BK) / (4 * THREADS);
    constexpr int NB4 = (BN * BK) / (4 * THREADS);
    constexpr int PA  = THREADS / BM;     // k4 passes for A
    constexpr int PB  = THREADS / BN;

    __shared__ __align__(16) float As[2][BK][BM];
    __shared__ __align__(16) float Bs[2][BK][2 * BN];

    const int tid = threadIdx.x;
    const int tx  = tid % NTX;
    const int ty  = tid / NTX;
    const int n0  = blockIdx.x * BN;
    const int m0  = blockIdx.y * BM;
    const float* Ab = A  + (size_t)blockIdx.z * a_bs;
    const float* Bb = Bm + (size_t)blockIdx.z * b_bs;
    float*       Cb = Cm + (size_t)blockIdx.z * c_bs;

    // global load mappings
    const int ar  = tid % BM;
    const int akc = tid / BM;
    const float* Ap = Ab + (size_t)(m0 + ar) * lda + akc * 4;

    int bn = 0, bkc = 0, bkr = 0, bn4 = 0;
    const float* Bp;
    if (!BNC) {
        bn  = tid % BN;
        bkc = tid / BN;
        Bp  = Bb + (size_t)(n0 + bn) * ldb + bkc * 4;
    } else {
        bkr = tid >> 5;            // 0..3
        bn4 = (tid & 31) * 4;      // 0..124
        Bp  = Bb + (size_t)bkr * ldb + n0 + bn4;
    }

    u64 acc[NP][TN];
#pragma unroll
    for (int p = 0; p < NP; p++)
#pragma unroll
        for (int j = 0; j < TN; j++) acc[p][j] = 0ull;

    float4 a_r[NA4], b_r[NB4];

    auto LOADA = [&](int kt) {
#pragma unroll
        for (int i = 0; i < NA4; i++)
            a_r[i] = *(const float4*)(Ap + (size_t)kt * BK + 4 * i * PA);
    };
    auto LOADB = [&](int kt) {
        if (!BNC) {
#pragma unroll
            for (int i = 0; i < NB4; i++)
                b_r[i] = *(const float4*)(Bp + (size_t)kt * BK + 4 * i * PB);
        } else {
#pragma unroll
            for (int i = 0; i < NB4; i++)
                b_r[i] = *(const float4*)(Bp + (size_t)(kt * BK + 4 * i) * ldb);
        }
    };
    auto STORE = [&](int buf) {
#pragma unroll
        for (int i = 0; i < NA4; i++) {
            int k4 = akc + i * PA;
            As[buf][4 * k4 + 0][ar] = a_r[i].x;
            As[buf][4 * k4 + 1][ar] = a_r[i].y;
            As[buf][4 * k4 + 2][ar] = a_r[i].z;
            As[buf][4 * k4 + 3][ar] = a_r[i].w;
        }
        if (!BNC) {
#pragma unroll
            for (int i = 0; i < NB4; i++) {
                int k4 = bkc + i * PB;
                *(float2*)&Bs[buf][4 * k4 + 0][2 * bn] = make_float2(b_r[i].x, b_r[i].x);
                *(float2*)&Bs[buf][4 * k4 + 1][2 * bn] = make_float2(b_r[i].y, b_r[i].y);
                *(float2*)&Bs[buf][4 * k4 + 2][2 * bn] = make_float2(b_r[i].z, b_r[i].z);
                *(float2*)&Bs[buf][4 * k4 + 3][2 * bn] = make_float2(b_r[i].w, b_r[i].w);
            }
        } else {
#pragma unroll
            for (int i = 0; i < NB4; i++) {
                int k = bkr + 4 * i;
                *(float2*)&Bs[buf][k][2 * (bn4 + 0)] = make_float2(b_r[i].x, b_r[i].x);
                *(float2*)&Bs[buf][k][2 * (bn4 + 1)] = make_float2(b_r[i].y, b_r[i].y);
                *(float2*)&Bs[buf][k][2 * (bn4 + 2)] = make_float2(b_r[i].z, b_r[i].z);
                *(float2*)&Bs[buf][k][2 * (bn4 + 3)] = make_float2(b_r[i].w, b_r[i].w);
            }
        }
    };

    LOADA(0); LOADB(0);
    STORE(0);
    __syncthreads();

    const int nt = K / BK;
    for (int it = 0; it < nt; it++) {
        const int cur = it & 1;
        if (it + 1 < nt) { LOADA(it + 1); LOADB(it + 1); }

#pragma unroll
        for (int k = 0; k < BK; k++) {
            const float* ask = &As[cur][k][ty * TM];
            const float* bsk = &Bs[cur][k][2 * tx];
            u64 bv[TN];
#pragma unroll
            for (int j = 0; j < TN; j++)
                bv[j] = *(const u64*)(bsk + j * 2 * NTX);
            u64 av[NP];
#pragma unroll
            for (int p = 0; p < NP; p++)
                av[p] = *(const u64*)(ask + 2 * p);
#pragma unroll
            for (int p = 0; p < NP; p++)
#pragma unroll
                for (int j = 0; j < TN; j++)
                    ffma2(acc[p][j], av[p], bv[j]);
        }

        if (it + 1 < nt) STORE(cur ^ 1);
        __syncthreads();
    }

    // epilogue
    float bj[TN];
#pragma unroll
    for (int j = 0; j < TN; j++)
        bj[j] = bias ? bias[n0 + j * NTX + tx] : 0.f;

#pragma unroll
    for (int p = 0; p < NP; p++) {
        int mA = m0 + ty * TM + 2 * p;
        int mB = mA + 1;
        size_t rA = swapf ? ((size_t)(mA & 63) * Tq + (mA >> 6)) : (size_t)mA;
        size_t rB = swapf ? ((size_t)(mB & 63) * Tq + (mB >> 6)) : (size_t)mB;
        float* cpa = Cb + rA * (size_t)ldc + n0;
        float* cpb = Cb + rB * (size_t)ldc + n0;
#pragma unroll
        for (int j = 0; j < TN; j++) {
            float2 f = u2f2(acc[p][j]);
            int off = j * NTX + tx;
            float va = f.x + bj[j];
            float vb = f.y + bj[j];
            if (accf) { va += cpa[off]; vb += cpb[off]; }
            cpa[off] = va;
            cpb[off] = vb;
        }
    }
}

// ---------------- small kernels ----------------------------------------------
__global__ void embed_k(const int* __restrict__ targets, const float* __restrict__ E)
{
    int m = blockIdx.x;                 // t*B + b
    int t = m >> 6, b = m & 63;
    int id = (t == 0) ? 0 : targets[b * Tq + (t - 1)];
    const float4* src = (const float4*)(E + (size_t)id * WEq);
    float4* dst = (float4*)(d_X + (size_t)m * WEq);
    dst[threadIdx.x] = src[threadIdx.x];
}

__global__ void words_k(const unsigned char* __restrict__ mask8)
{
    int b = blockIdx.x, t = threadIdx.x;
    int is8 = (mask8[1] != 0);
    int v;
    if (is8) v = mask8[b * Tq + t] ? 1 : 0;
    else     v = ((const int*)mask8)[b * Tq + t] ? 1 : 0;
#pragma unroll
    for (int o = 16; o; o >>= 1) v += __shfl_down_sync(0xffffffffu, v, o);
    __shared__ int red[8];
    if ((t & 31) == 0) red[t >> 5] = v;
    __syncthreads();
    if (t == 0) {
        int s = 0;
#pragma unroll
        for (int i = 0; i < 8; i++) s += red[i];
        d_words[b] = s;
    }
}

__global__ void h0_k(const float* __restrict__ enc)
{
    int b = blockIdx.x;
    const float4* src = (const float4*)(enc + ((size_t)b * Tq + (Tq - 1)) * Hq);
    float4* dst = (float4*)(d_H + (size_t)b * Hq);
    dst[threadIdx.x] = src[threadIdx.x];
}

__global__ void gates_k(const float* __restrict__ b_hh, int t)
{
    int idx = blockIdx.x * 256 + threadIdx.x;
    int b = idx >> 10;
    int j = idx & (Hq - 1);
    float ghr = b_hh[j], ghz = b_hh[Hq + j], ghn = b_hh[2 * Hq + j];
#pragma unroll
    for (int s = 0; s < SPLITS; s++) {
        const float* p = d_ghp + (size_t)s * Bq * G3q + (size_t)b * G3q;
        ghr += p[j]; ghz += p[Hq + j]; ghn += p[2 * Hq + j];
    }
    const float* gi = d_gi + ((size_t)t * Bq + b) * G3q;
    float r = 1.f / (1.f + expf(-(gi[j]          + ghr)));
    float z = 1.f / (1.f + expf(-(gi[Hq + j]     + ghz)));
    float n = tanhf(gi[2 * Hq + j] + r * ghn);
    float hp = d_H[(size_t)t * Bq * Hq + (size_t)b * Hq + j];
    d_H[(size_t)(t + 1) * Bq * Hq + (size_t)b * Hq + j] = (1.f - z) * n + z * hp;
}

__global__ void softmax_k()
{
    int m = blockIdx.x;                 // t*B + b
    int b = m & (Bq - 1);
    int wn = d_words[b];
    float* e = d_e + (size_t)m * Tq;
    int s = threadIdx.x;
    float v = (s < wn) ? e[s] : -3.0e38f;

    __shared__ float red[8];
    __shared__ float smax, ssum;
    float mx = v;
#pragma unroll
    for (int o = 16; o; o >>= 1) mx = fmaxf(mx, __shfl_xor_sync(0xffffffffu, mx, o));
    if ((s & 31) == 0) red[s >> 5] = mx;
    __syncthreads();
    if (s == 0) {
        float x = red[0];
#pragma unroll
        for (int i = 1; i < 8; i++) x = fmaxf(x, red[i]);
        smax = x;
    }
    __syncthreads();
    float ex = (s < wn) ? expf(v - smax) : 0.f;
    float sum = ex;
#pragma unroll
    for (int o = 16; o; o >>= 1) sum += __shfl_xor_sync(0xffffffffu, sum, o);
    if ((s & 31) == 0) red[s >> 5] = sum;
    __syncthreads();
    if (s == 0) {
        float x = 0.f;
#pragma unroll
        for (int i = 0; i < 8; i++) x += red[i];
        ssum = 1.f / x;
    }
    __syncthreads();
    e[s] = ex * ssum;
}

// ---------------- launch ------------------------------------------------------
extern "C" void kernel_launch(void* const* d_in, const int* in_sizes, int n_in,
                              void* d_out, int out_size)
{
    const float*         enc     = (const float*)d_in[0];
    const unsigned char* mask    = (const unsigned char*)d_in[1];
    const int*           targets = (const int*)d_in[2];
    const float*         E       = (const float*)d_in[3];
    const float*         W_ih    = (const float*)d_in[4];
    const float*         W_hh    = (const float*)d_in[5];
    const float*         b_ih    = (const float*)d_in[6];
    const float*         b_hh    = (const float*)d_in[7];
    const float*         W_out   = (const float*)d_in[8];
    const float*         b_out   = (const float*)d_in[9];
    float* out = (float*)d_out;

    void* p;
    cudaGetSymbolAddress(&p, d_X);   float* X   = (float*)p;
    cudaGetSymbolAddress(&p, d_gi);  float* GI  = (float*)p;
    cudaGetSymbolAddress(&p, d_H);   float* Hh  = (float*)p;
    cudaGetSymbolAddress(&p, d_ghp); float* GHP = (float*)p;
    cudaGetSymbolAddress(&p, d_e);   float* Ee  = (float*)p;
    cudaGetSymbolAddress(&p, d_ctx); float* CTX = (float*)p;

    // Phase 0
    embed_k<<<Tq * Bq, 64>>>(targets, E);
    words_k<<<Bq, 256>>>(mask);
    h0_k<<<Bq, 256>>>(enc);

    // Phase 1: gi = X @ W_ih^T + b_ih   (16384 x 3072 x 256)
    gemm2_k<128, 128, 16, 8, false><<<dim3(G3q / 128, (Tq * Bq) / 128, 1), 128>>>(
        X, W_ih, GI, WEq, WEq, WEq, G3q, 0, 0, 0, b_ih, 0, 0);

    // Phase 2: sequential GRU
    for (int t = 0; t < Tq; t++) {
        gemm2_k<64, 64, 8, 4, false><<<dim3(G3q / 64, 1, SPLITS), 128>>>(
            Hh + (size_t)t * Bq * Hq, W_hh, GHP, Hq / SPLITS,
            Hq, Hq, G3q,
            Hq / SPLITS, Hq / SPLITS, (long long)Bq * G3q,
            nullptr, 0, 0);
        gates_k<<<(Bq * Hq) / 256, 256>>>(b_hh, t);
    }

    // Phase 3a: e scores
    gemm2_k<128, 128, 16, 8, false><<<dim3(Tq / 128, Tq / 128, Bq), 128>>>(
        Hh + (size_t)Bq * Hq, enc, Ee, Hq,
        Bq * Hq, Hq, Bq * Tq,
        Hq, (long long)Tq * Hq, Tq,
        nullptr, 0, 0);

    // Phase 3b: masked softmax
    softmax_k<<<Tq * Bq, Tq>>>();

    // Phase 3c: contexts (B n-contiguous)
    gemm2_k<128, 128, 16, 8, true><<<dim3(Hq / 128, Tq / 128, Bq), 128>>>(
        Ee, enc, CTX, Tq,
        Bq * Tq, Hq, Bq * Hq,
        Tq, (long long)Tq * Hq, Hq,
        nullptr, 0, 0);

    // Phase 4: logits (written in (B, T, C) order via swapf)
    gemm2_k<128, 128, 16, 8, false><<<dim3(Cq / 128, (Tq * Bq) / 128, 1), 128>>>(
        Hh + (size_t)Bq * Hq, W_out, out, Hq,
        Hq, 2 * Hq, Cq, 0, 0, 0, b_out, 0, 1);
    gemm2_k<128, 128, 16, 8, false><<<dim3(Cq / 128, (Tq * Bq) / 128, 1), 128>>>(
        CTX, W_out + Hq, out, Hq,
        Hq, 2 * Hq, Cq, 0, 0, 0, nullptr, 1, 1);
}